// round 2
// baseline (speedup 1.0000x reference)
#include <cuda_runtime.h>
#include <math.h>

// ---------------------------------------------------------------------------
// Euler_34093450396545: batched Euler integration of a forced oscillator-coupled
// z-recursion, followed by per-row min-max rescale.
//
// Key structural facts exploited:
//  * The (x,y) limit-cycle recursion is identical for every batch row
//    (x0,y0 are constants, x/y never read z or the params) -> precompute
//    theta_n = atan2(y_n,x_n) and H*z0(t_n) ONCE in a tiny kernel.
//  * fmod(th - theta, 2pi) == th - theta since |th - theta| < pi + 1 < 2pi.
//  * exp(-d^2/(2b^2)) == exp2(k*d^2) with k = -log2(e)/(2 b^2) precomputed
//    per row -> single EX2.APPROX per gaussian, no FMUL-by-log2e per step.
//  * Full trajectory buffered in SMEM (128 rows x stride 217, bank-conflict
//    free), min/max tracked in registers -> single coalesced HBM write.
// ---------------------------------------------------------------------------

#define NSTEPS 216
#define RPB 128           // rows per block (= threads per block)
#define ZSTRIDE 217       // 217 mod 32 = 25, gcd(25,32)=1 -> conflict free

static __device__ float2 g_tbl[NSTEPS];   // .x = theta_n, .y = H * z0_n

// ---- kernel 1: shared (theta_n, H*z0_n) table --------------------------------
__global__ void table_kernel() {
    const int tid = threadIdx.x;
    const float H     = 1.0f / 216.0f;
    const float OMEGA = 6.283185307179586f;   // 2*pi (fp32)
    float x = -0.417750770388669f;
    float y = -0.9085616622823985f;
    float mx = x, my = y;
    // Every thread redundantly runs the full recursion in registers; thread n
    // records the carry ENTERING step n (that's what atan2 sees in the ref).
    for (int n = 0; n < NSTEPS; ++n) {
        if (n == tid) { mx = x; my = y; }
        float r     = sqrtf(x * x + y * y);
        float alpha = 1.0f - r;
        float fx = alpha * x - OMEGA * y;
        float fy = alpha * y + OMEGA * x;
        x = x + H * fx;
        y = y + H * fy;
    }
    if (tid < NSTEPS) {
        float th = atan2f(my, mx);
        // z0(t) = A_Z0 * sin(2*pi*F2*t), t = n/216, 2*pi*0.25 = pi/2
        float t  = (float)tid * (1.0f / 216.0f);
        float z0 = 0.005f * sinf(1.5707963267948966f * t);
        g_tbl[tid] = make_float2(th, H * z0);
    }
}

// ---- kernel 2: main integration ---------------------------------------------
__global__ void __launch_bounds__(RPB, 2)
euler_kernel(const float* __restrict__ xin, const float* __restrict__ v0,
             float* __restrict__ out) {
    extern __shared__ float smem[];
    float*  sz     = smem;                                   // RPB*ZSTRIDE floats
    float2* stbl   = (float2*)(smem + RPB * ZSTRIDE);        // NSTEPS float2
    float*  sscale = (float*)(stbl + NSTEPS);                // RPB
    float*  sbase  = sscale + RPB;                           // RPB

    const int tid  = threadIdx.x;
    const int row0 = blockIdx.x * RPB;

    // stage table into shared
    for (int i = tid; i < NSTEPS; i += RPB) stbl[i] = g_tbl[i];

    // stage this block's 128x15 params coalesced through shared (reuse sz)
    const float* xrow = xin + (size_t)row0 * 15;
    for (int i = tid; i < RPB * 15; i += RPB) sz[i] = xrow[i];
    __syncthreads();

    const float H = 1.0f / 216.0f;
    float aH[5], th0[5], kk[5];
    #pragma unroll
    for (int j = 0; j < 5; ++j) {
        float a  = sz[tid * 15 + 3 * j + 0];
        float b  = sz[tid * 15 + 3 * j + 1];
        th0[j]   = sz[tid * 15 + 3 * j + 2];
        aH[j]    = -H * a;                                   // fold -H into a
        kk[j]    = -1.4426950408889634f / (2.0f * b * b);    // fold log2e
    }
    float z = v0[row0 + tid];
    __syncthreads();   // params fully read before sz is reused for trajectory

    float* myz = sz + tid * ZSTRIDE;
    float zmin =  3.402823466e38f;
    float zmax = -3.402823466e38f;
    const float ONE_MINUS_H = 1.0f - (1.0f / 216.0f);

    #pragma unroll 4
    for (int n = 0; n < NSTEPS; ++n) {
        float2 tb  = stbl[n];          // broadcast LDS.64
        float  th  = tb.x;
        float  acc = tb.y;             // starts at H*z0_n
        #pragma unroll
        for (int j = 0; j < 5; ++j) {
            float dth = th - th0[j];
            float q   = kk[j] * dth;
            float arg = q * dth;       // k * dth^2 (in log2 domain)
            float e;
            asm("ex2.approx.ftz.f32 %0, %1;" : "=f"(e) : "f"(arg));
            acc = fmaf(aH[j] * dth, e, acc);
        }
        z = fmaf(z, ONE_MINUS_H, acc); // z*(1-H) + H*z0 - H*sum(gauss)
        zmin = fminf(zmin, z);
        zmax = fmaxf(zmax, z);
        myz[n] = z;
    }

    // per-row affine: out = z*scale + base
    {
        float scale = 0.042557f / (zmax - zmin);
        sscale[tid] = scale;
        sbase[tid]  = fmaf(-zmin, scale, -0.01563f);
    }
    __syncthreads();

    // coalesced, transposed epilogue: consecutive threads -> consecutive t
    float* orow = out + (size_t)row0 * NSTEPS;
    for (int i = tid; i < RPB * NSTEPS; i += RPB) {
        int r = i / NSTEPS;
        int t = i - r * NSTEPS;
        float zv = sz[r * ZSTRIDE + t];
        orow[i] = fmaf(zv, sscale[r], sbase[r]);
    }
}

// ---------------------------------------------------------------------------
extern "C" void kernel_launch(void* const* d_in, const int* in_sizes, int n_in,
                              void* d_out, int out_size) {
    const float* x  = (const float*)d_in[0];   // (B, 15)
    const float* v0 = (const float*)d_in[1];   // (B,)
    float* out = (float*)d_out;                // (B, 216)

    int B = in_sizes[1];                       // element count of v0 = batch
    int nblocks = B / RPB;                     // B = 131072 -> 1024

    const unsigned smem_bytes =
        (RPB * ZSTRIDE + 2 * NSTEPS + 2 * RPB) * sizeof(float);  // 113856 B

    cudaFuncSetAttribute(euler_kernel,
                         cudaFuncAttributeMaxDynamicSharedMemorySize,
                         smem_bytes);

    table_kernel<<<1, 256>>>();
    euler_kernel<<<nblocks, RPB, smem_bytes>>>(x, v0, out);
}

// round 3
// speedup vs baseline: 1.1525x; 1.1525x over previous
#include <cuda_runtime.h>
#include <math.h>

// ---------------------------------------------------------------------------
// Euler_34093450396545, round 2.
// R1 post-mortem: occ=11.5% (smem trajectory buffer caps at 8 warps/SM),
// issue=47% -> latency-bound. Fix: two-pass recompute (no trajectory storage)
// + f32x2 packed math (2 rows/thread) so the doubled FLOPs cost the same
// fma-pipe time. Predicted bound: MUFU/EX2 ~60us.
// ---------------------------------------------------------------------------

#define NSTEPS  216
#define TPB     128          // threads per block
#define ROWSPB  256          // rows per block (2 rows / thread, packed)
#define CHUNK   8            // steps per output staging flush
#define CSTRIDE 264          // floats per chunk-step row (264*4 % bank-safe)

typedef unsigned long long u64;

// packed helpers ------------------------------------------------------------
static __device__ __forceinline__ u64 pk(float x, float y) {
    u64 r; asm("mov.b64 %0,{%1,%2};" : "=l"(r) : "f"(x), "f"(y)); return r;
}
static __device__ __forceinline__ float2 upk(u64 v) {
    float2 f; asm("mov.b64 {%0,%1},%2;" : "=f"(f.x), "=f"(f.y) : "l"(v)); return f;
}
static __device__ __forceinline__ u64 fadd2(u64 a, u64 b) {
    u64 d; asm("add.rn.f32x2 %0,%1,%2;" : "=l"(d) : "l"(a), "l"(b)); return d;
}
static __device__ __forceinline__ u64 fmul2(u64 a, u64 b) {
    u64 d; asm("mul.rn.f32x2 %0,%1,%2;" : "=l"(d) : "l"(a), "l"(b)); return d;
}
static __device__ __forceinline__ u64 ffma2(u64 a, u64 b, u64 c) {
    u64 d; asm("fma.rn.f32x2 %0,%1,%2,%3;" : "=l"(d) : "l"(a), "l"(b), "l"(c)); return d;
}
static __device__ __forceinline__ float ex2f(float x) {
    float e; asm("ex2.approx.ftz.f32 %0,%1;" : "=f"(e) : "f"(x)); return e;
}

// table: .x = packed {theta_n, theta_n}, .y = packed {H*z0_n, H*z0_n} --------
static __device__ ulonglong2 g_tbl[NSTEPS];

__global__ void table_kernel() {
    const int tid = threadIdx.x;
    const float H     = 1.0f / 216.0f;
    const float OMEGA = 6.283185307179586f;
    float x = -0.417750770388669f;
    float y = -0.9085616622823985f;
    float mx = x, my = y;
    for (int n = 0; n < NSTEPS; ++n) {
        if (n == tid) { mx = x; my = y; }
        float r     = sqrtf(x * x + y * y);
        float alpha = 1.0f - r;
        float fx = alpha * x - OMEGA * y;
        float fy = alpha * y + OMEGA * x;
        x = x + H * fx;
        y = y + H * fy;
    }
    if (tid < NSTEPS) {
        float th = atan2f(my, mx);
        float t  = (float)tid * (1.0f / 216.0f);
        float z0 = 0.005f * sinf(1.5707963267948966f * t);  // 2pi*F2 = pi/2
        float hz = H * z0;
        g_tbl[tid].x = pk(th, th);
        g_tbl[tid].y = pk(hz, hz);
    }
}

// ---------------------------------------------------------------------------
// Per-step body: z' = z*(1-H) + H*z0_n + sum_j (-H*a_j)*dth*exp2(k_j*dth^2)
// All math packed f32x2 (2 independent rows per thread).
// ---------------------------------------------------------------------------
static __device__ __forceinline__ u64 step_body(
    u64 z, ulonglong2 tb, const u64* nth0, const u64* kk, const u64* aH,
    u64 OMH2)
{
    u64 acc = tb.y;
    #pragma unroll
    for (int j = 0; j < 5; ++j) {
        u64 dth = fadd2(tb.x, nth0[j]);        // th - th0
        u64 d2  = fmul2(dth, dth);
        u64 arg = fmul2(kk[j], d2);            // k*dth^2 (log2 domain)
        float2 af = upk(arg);
        u64 e   = pk(ex2f(af.x), ex2f(af.y));
        u64 t   = fmul2(aH[j], dth);
        acc = ffma2(t, e, acc);
    }
    return ffma2(z, OMH2, acc);
}

__global__ void __launch_bounds__(TPB)
euler_kernel(const float* __restrict__ xin, const float* __restrict__ v0,
             float* __restrict__ out) {
    __shared__ ulonglong2 stbl[NSTEPS];
    __shared__ float      schunk[CHUNK * CSTRIDE];
    __shared__ float      sparams[ROWSPB * 15];

    const int tid  = threadIdx.x;
    const int row0 = blockIdx.x * ROWSPB;

    for (int i = tid; i < NSTEPS; i += TPB) stbl[i] = g_tbl[i];
    {
        const float* xrow = xin + (size_t)row0 * 15;
        for (int i = tid; i < ROWSPB * 15; i += TPB) sparams[i] = xrow[i];
    }
    __syncthreads();

    const float H = 1.0f / 216.0f;
    u64 nth0[5], kk[5], aH[5];
    {
        const float* p0 = sparams + (2 * tid)     * 15;
        const float* p1 = sparams + (2 * tid + 1) * 15;
        #pragma unroll
        for (int j = 0; j < 5; ++j) {
            float a0 = p0[3 * j], b0 = p0[3 * j + 1], t0 = p0[3 * j + 2];
            float a1 = p1[3 * j], b1 = p1[3 * j + 1], t1 = p1[3 * j + 2];
            nth0[j] = pk(-t0, -t1);
            aH[j]   = pk(-H * a0, -H * a1);
            kk[j]   = pk(-1.4426950408889634f / (2.0f * b0 * b0),
                         -1.4426950408889634f / (2.0f * b1 * b1));
        }
    }
    const float omh = 1.0f - H;
    const u64 OMH2 = pk(omh, omh);

    u64 z0;
    {
        const float2* v2 = (const float2*)v0;
        float2 vv = v2[(row0 >> 1) + tid];   // coalesced LD.64
        z0 = pk(vv.x, vv.y);
    }

    // ---- pass 1: min/max only (registers) --------------------------------
    float mn0 =  3.402823466e38f, mn1 =  3.402823466e38f;
    float mx0 = -3.402823466e38f, mx1 = -3.402823466e38f;
    {
        u64 z = z0;
        #pragma unroll 4
        for (int n = 0; n < NSTEPS; ++n) {
            z = step_body(z, stbl[n], nth0, kk, aH, OMH2);
            float2 zf = upk(z);
            mn0 = fminf(mn0, zf.x); mx0 = fmaxf(mx0, zf.x);
            mn1 = fminf(mn1, zf.y); mx1 = fmaxf(mx1, zf.y);
        }
    }
    u64 sc, bs;
    {
        float s0 = 0.042557f / (mx0 - mn0);
        float s1 = 0.042557f / (mx1 - mn1);
        sc = pk(s0, s1);
        bs = pk(fmaf(-mn0, s0, -0.01563f), fmaf(-mn1, s1, -0.01563f));
    }

    // ---- pass 2: identical recompute, scaled + staged coalesced write ----
    {
        u64 z = z0;
        float* obase = out + (size_t)row0 * NSTEPS;
        for (int ch = 0; ch < NSTEPS / CHUNK; ++ch) {
            #pragma unroll
            for (int c = 0; c < CHUNK; ++c) {
                int n = ch * CHUNK + c;
                z = step_body(z, stbl[n], nth0, kk, aH, OMH2);
                u64 o = ffma2(z, sc, bs);
                // [step][row] layout, 64-bit store of the row pair
                *reinterpret_cast<u64*>(schunk + c * CSTRIDE + 2 * tid) = o;
            }
            __syncthreads();
            #pragma unroll
            for (int k = 0; k < (ROWSPB * CHUNK) / TPB; ++k) {
                int i = tid + k * TPB;
                int r = i >> 3;          // local row
                int c = i & 7;           // step-in-chunk
                obase[r * NSTEPS + ch * CHUNK + c] = schunk[c * CSTRIDE + r];
            }
            __syncthreads();
        }
    }
}

// ---------------------------------------------------------------------------
extern "C" void kernel_launch(void* const* d_in, const int* in_sizes, int n_in,
                              void* d_out, int out_size) {
    const float* x  = (const float*)d_in[0];   // (B, 15)
    const float* v0 = (const float*)d_in[1];   // (B,)
    float* out = (float*)d_out;                // (B, 216)

    int B = in_sizes[1];
    int nblocks = B / ROWSPB;                  // 131072 / 256 = 512

    table_kernel<<<1, 256>>>();
    euler_kernel<<<nblocks, TPB>>>(x, v0, out);
}

// round 4
// speedup vs baseline: 2.2130x; 1.9203x over previous
#include <cuda_runtime.h>
#include <math.h>

// ---------------------------------------------------------------------------
// Euler_34093450396545, round 3.
// R2 post-mortem: 148us, issue=47%, fma=48%. Fixes:
//  * (theta_n, H*z0_n) table computed at COMPILE TIME (constexpr fp32-emulated
//    recursion) into __constant__ -> table_kernel launch (~15us) eliminated.
//  * Each gaussian fused into one asm block (6 packed f32x2 fma-ops + 2 ex2,
//    acc ffma folded in) -> pack/unpack mov traffic minimized.
//  * Two interleaved accumulators, TPB=256 single wave, conflict-free staging.
// ---------------------------------------------------------------------------

#define NSTEPS  216
#define TPB     256
#define ROWSPB  512          // 2 rows / thread, f32x2 packed
#define CHUNK   8
#define CSTRIDE 516          // = 4 (mod 32) -> bank-bijective transpose read

typedef unsigned long long u64;

// ======================= compile-time table ================================
namespace ct {
constexpr double PI = 3.14159265358979323846264338327950288;

constexpr double dsqrt(double x) {
    double y = x > 1.0 ? x : 1.0;
    for (int i = 0; i < 48; ++i) y = 0.5 * (y + x / y);
    return y;
}
constexpr double datan(double t) {
    double s = 1.0;
    for (int i = 0; i < 3; ++i) { t = t / (1.0 + dsqrt(1.0 + t * t)); s *= 2.0; }
    double t2 = t * t, r = 0.0;
    for (int k = 12; k >= 0; --k) r = 1.0 / (2.0 * k + 1.0) - t2 * r;
    return s * t * r;
}
constexpr double datan2(double y, double x) {
    if (x > 0.0) return datan(y / x);
    if (x < 0.0) return (y >= 0.0) ? datan(y / x) + PI : datan(y / x) - PI;
    return (y > 0.0) ? PI / 2 : -PI / 2;
}
constexpr double dsin(double x) {
    double x2 = x * x, term = x, sum = x;
    for (int k = 1; k <= 14; ++k) { term *= -x2 / ((2.0 * k) * (2.0 * k + 1.0)); sum += term; }
    return sum;
}
// fp32 rounding emulation: products/sums of floats are exact in double,
// the (float) cast performs the single IEEE-RN rounding of the fp32 op.
constexpr float f32(double x) { return (float)x; }

struct CTable { float v[NSTEPS][4]; };   // {th, th, hz, hz} per step

constexpr CTable make_table() {
    CTable T{};
    const float H     = f32(1.0 / 216.0);
    const float OMEGA = f32(2.0 * PI);
    const float PIH   = f32(0.5 * PI);        // (2*pi*F2) rounded to f32
    float x = f32(-0.417750770388669);
    float y = f32(-0.9085616622823985);
    for (int n = 0; n < NSTEPS; ++n) {
        float th = f32(datan2((double)y, (double)x));      // carry ENTERING step n
        float t   = f32((double)n / 216.0);
        float arg = f32((double)PIH * (double)t);
        float s   = f32(dsin((double)arg));
        float z0  = f32((double)f32(0.005) * (double)s);
        float hz  = f32((double)H * (double)z0);
        T.v[n][0] = th; T.v[n][1] = th;
        T.v[n][2] = hz; T.v[n][3] = hz;
        // fp32-emulated limit-cycle step
        float xx = f32((double)x * (double)x);
        float yy = f32((double)y * (double)y);
        float s2 = f32((double)xx + (double)yy);
        float r  = f32(dsqrt((double)s2));
        float al = f32(1.0 - (double)r);
        float ax = f32((double)al * (double)x);
        float oy = f32((double)OMEGA * (double)y);
        float fx = f32((double)ax - (double)oy);
        float ay = f32((double)al * (double)y);
        float ox = f32((double)OMEGA * (double)x);
        float fy = f32((double)ay + (double)ox);
        float hx = f32((double)H * (double)fx);
        float hy = f32((double)H * (double)fy);
        x = f32((double)x + (double)hx);
        y = f32((double)y + (double)hy);
    }
    return T;
}
constexpr CTable h_tbl = make_table();
} // namespace ct

__constant__ ct::CTable c_tbl = ct::h_tbl;

// ======================= packed helpers ====================================
static __device__ __forceinline__ u64 pk(float x, float y) {
    u64 r; asm("mov.b64 %0,{%1,%2};" : "=l"(r) : "f"(x), "f"(y)); return r;
}
static __device__ __forceinline__ float2 upk(u64 v) {
    float2 f; asm("mov.b64 {%0,%1},%2;" : "=f"(f.x), "=f"(f.y) : "l"(v)); return f;
}
static __device__ __forceinline__ u64 fadd2(u64 a, u64 b) {
    u64 d; asm("add.rn.f32x2 %0,%1,%2;" : "=l"(d) : "l"(a), "l"(b)); return d;
}
static __device__ __forceinline__ u64 ffma2(u64 a, u64 b, u64 c) {
    u64 d; asm("fma.rn.f32x2 %0,%1,%2,%3;" : "=l"(d) : "l"(a), "l"(b), "l"(c)); return d;
}

// one gaussian, fully fused: acc += (aH*dth) * exp2(k*dth^2)
static __device__ __forceinline__ u64 gauss_acc(u64 acc, u64 thp, u64 nth0,
                                                u64 kkj, u64 aHj) {
    u64 r;
    asm("{\n\t"
        ".reg .b64 d,q,g;\n\t"
        ".reg .b32 al,ah;\n\t"
        "add.rn.f32x2 d,%1,%2;\n\t"        // dth = th - th0
        "mul.rn.f32x2 q,%3,d;\n\t"         // k*dth
        "mul.rn.f32x2 q,q,d;\n\t"          // arg = k*dth^2
        "mov.b64 {al,ah},q;\n\t"
        "ex2.approx.ftz.f32 al,al;\n\t"
        "ex2.approx.ftz.f32 ah,ah;\n\t"
        "mov.b64 g,{al,ah};\n\t"
        "mul.rn.f32x2 d,%4,d;\n\t"         // t = aH*dth
        "fma.rn.f32x2 %0,d,g,%5;\n\t"      // acc += t*e
        "}"
        : "=l"(r) : "l"(thp), "l"(nth0), "l"(kkj), "l"(aHj), "l"(acc));
    return r;
}

// forcing for step n (independent of z): hz0_n - H*sum(gauss)
static __device__ __forceinline__ u64 forcing(int n, const u64* nth0,
                                              const u64* kk, const u64* aH) {
    float4 e = reinterpret_cast<const float4*>(c_tbl.v)[n];   // uniform LDC.128
    u64 thp = pk(e.x, e.y);
    u64 a0  = pk(e.z, e.w);                                   // hz seed
    u64 a1  = gauss_acc(0ull, thp, nth0[1], kk[1], aH[1]);    // second chain
    a0 = gauss_acc(a0, thp, nth0[0], kk[0], aH[0]);
    a1 = gauss_acc(a1, thp, nth0[3], kk[3], aH[3]);
    a0 = gauss_acc(a0, thp, nth0[2], kk[2], aH[2]);
    a1 = gauss_acc(a1, thp, nth0[4], kk[4], aH[4]);
    return fadd2(a0, a1);
}

// ======================= main kernel =======================================
__global__ void __launch_bounds__(TPB, 2)
euler_kernel(const float* __restrict__ xin, const float* __restrict__ v0,
             float* __restrict__ out) {
    __shared__ float schunk[CHUNK * CSTRIDE];

    const int tid  = threadIdx.x;
    const int row0 = blockIdx.x * ROWSPB;

    // per-thread params for rows (row0+2tid, row0+2tid+1), direct coalesced-ish
    const float H = 1.0f / 216.0f;
    u64 nth0[5], kk[5], aH[5];
    {
        const float* p0 = xin + (size_t)(row0 + 2 * tid) * 15;
        const float* p1 = p0 + 15;
        #pragma unroll
        for (int j = 0; j < 5; ++j) {
            float a0 = p0[3 * j], b0 = p0[3 * j + 1], t0 = p0[3 * j + 2];
            float a1 = p1[3 * j], b1 = p1[3 * j + 1], t1 = p1[3 * j + 2];
            nth0[j] = pk(-t0, -t1);
            aH[j]   = pk(-H * a0, -H * a1);
            kk[j]   = pk(-1.4426950408889634f / (2.0f * b0 * b0),
                         -1.4426950408889634f / (2.0f * b1 * b1));
        }
    }
    const float omh = 1.0f - H;
    const u64 OMH2 = pk(omh, omh);

    u64 z0;
    {
        float2 vv = reinterpret_cast<const float2*>(v0)[(row0 >> 1) + tid];
        z0 = pk(vv.x, vv.y);
    }

    // ---- pass 1: min/max only --------------------------------------------
    float mn0 =  3.402823466e38f, mn1 =  3.402823466e38f;
    float mx0 = -3.402823466e38f, mx1 = -3.402823466e38f;
    {
        u64 z = z0;
        #pragma unroll 8
        for (int n = 0; n < NSTEPS; ++n) {
            u64 f = forcing(n, nth0, kk, aH);
            z = ffma2(z, OMH2, f);
            float2 zf = upk(z);
            mn0 = fminf(mn0, zf.x); mx0 = fmaxf(mx0, zf.x);
            mn1 = fminf(mn1, zf.y); mx1 = fmaxf(mx1, zf.y);
        }
    }
    u64 sc, bs;
    {
        float s0 = 0.042557f / (mx0 - mn0);
        float s1 = 0.042557f / (mx1 - mn1);
        sc = pk(s0, s1);
        bs = pk(fmaf(-mn0, s0, -0.01563f), fmaf(-mn1, s1, -0.01563f));
    }

    // ---- pass 2: bit-identical recompute + staged coalesced write --------
    {
        u64 z = z0;
        float* obase = out + (size_t)row0 * NSTEPS;
        for (int ch = 0; ch < NSTEPS / CHUNK; ++ch) {
            #pragma unroll
            for (int c = 0; c < CHUNK; ++c) {
                u64 f = forcing(ch * CHUNK + c, nth0, kk, aH);
                z = ffma2(z, OMH2, f);
                u64 o = ffma2(z, sc, bs);
                *reinterpret_cast<u64*>(&schunk[c * CSTRIDE + 2 * tid]) = o;
            }
            __syncthreads();
            #pragma unroll
            for (int k = 0; k < (ROWSPB * CHUNK) / TPB; ++k) {
                int i = tid + k * TPB;
                int r = i >> 3;                 // local row 0..511
                int c = i & 7;                  // step-in-chunk
                obase[r * NSTEPS + ch * CHUNK + c] = schunk[c * CSTRIDE + r];
            }
            __syncthreads();
        }
    }
}

// ---------------------------------------------------------------------------
extern "C" void kernel_launch(void* const* d_in, const int* in_sizes, int n_in,
                              void* d_out, int out_size) {
    const float* x  = (const float*)d_in[0];   // (B, 15)
    const float* v0 = (const float*)d_in[1];   // (B,)
    float* out = (float*)d_out;                // (B, 216)

    int B = in_sizes[1];
    int nblocks = B / ROWSPB;                  // 131072 / 512 = 256

    euler_kernel<<<nblocks, TPB>>>(x, v0, out);
}

// round 5
// speedup vs baseline: 2.3109x; 1.0442x over previous
#include <cuda_runtime.h>
#include <math.h>

// ---------------------------------------------------------------------------
// Euler_34093450396545, round 4.
// R3 post-mortem: 77us, issue=53%, fma=54%, occ=18.7%. Neither pipe saturated;
// grid=256 over 148 SMs gave 15.6% load imbalance (2 vs 1 CTAs/SM).
// Fixes:
//  * TPB=64, ROWSPB=128, grid=1024, launch_bounds(64,8): 8 resident CTAs/SM,
//    6.92 avg blocks/SM -> ~1% imbalance (was 15.6%), finer scheduling grain.
//  * Coalesced smem staging of the (row,15) params (was scattered stride-15 LDG).
// Everything else (compile-time table, fused f32x2 gaussians, two-pass
// recompute, staged coalesced output) unchanged.
// ---------------------------------------------------------------------------

#define NSTEPS  216
#define TPB     64
#define ROWSPB  128          // 2 rows / thread, f32x2 packed
#define CHUNK   8
#define CSTRIDE 132          // = 4 (mod 32) -> bank-bijective transpose read

typedef unsigned long long u64;

// ======================= compile-time table ================================
namespace ct {
constexpr double PI = 3.14159265358979323846264338327950288;

constexpr double dsqrt(double x) {
    double y = x > 1.0 ? x : 1.0;
    for (int i = 0; i < 48; ++i) y = 0.5 * (y + x / y);
    return y;
}
constexpr double datan(double t) {
    double s = 1.0;
    for (int i = 0; i < 3; ++i) { t = t / (1.0 + dsqrt(1.0 + t * t)); s *= 2.0; }
    double t2 = t * t, r = 0.0;
    for (int k = 12; k >= 0; --k) r = 1.0 / (2.0 * k + 1.0) - t2 * r;
    return s * t * r;
}
constexpr double datan2(double y, double x) {
    if (x > 0.0) return datan(y / x);
    if (x < 0.0) return (y >= 0.0) ? datan(y / x) + PI : datan(y / x) - PI;
    return (y > 0.0) ? PI / 2 : -PI / 2;
}
constexpr double dsin(double x) {
    double x2 = x * x, term = x, sum = x;
    for (int k = 1; k <= 14; ++k) { term *= -x2 / ((2.0 * k) * (2.0 * k + 1.0)); sum += term; }
    return sum;
}
constexpr float f32(double x) { return (float)x; }

struct CTable { float v[NSTEPS][4]; };   // {th, th, hz, hz}

constexpr CTable make_table() {
    CTable T{};
    const float H     = f32(1.0 / 216.0);
    const float OMEGA = f32(2.0 * PI);
    const float PIH   = f32(0.5 * PI);
    float x = f32(-0.417750770388669);
    float y = f32(-0.9085616622823985);
    for (int n = 0; n < NSTEPS; ++n) {
        float th = f32(datan2((double)y, (double)x));
        float t   = f32((double)n / 216.0);
        float arg = f32((double)PIH * (double)t);
        float s   = f32(dsin((double)arg));
        float z0  = f32((double)f32(0.005) * (double)s);
        float hz  = f32((double)H * (double)z0);
        T.v[n][0] = th; T.v[n][1] = th;
        T.v[n][2] = hz; T.v[n][3] = hz;
        float xx = f32((double)x * (double)x);
        float yy = f32((double)y * (double)y);
        float s2 = f32((double)xx + (double)yy);
        float r  = f32(dsqrt((double)s2));
        float al = f32(1.0 - (double)r);
        float ax = f32((double)al * (double)x);
        float oy = f32((double)OMEGA * (double)y);
        float fx = f32((double)ax - (double)oy);
        float ay = f32((double)al * (double)y);
        float ox = f32((double)OMEGA * (double)x);
        float fy = f32((double)ay + (double)ox);
        float hx = f32((double)H * (double)fx);
        float hy = f32((double)H * (double)fy);
        x = f32((double)x + (double)hx);
        y = f32((double)y + (double)hy);
    }
    return T;
}
constexpr CTable h_tbl = make_table();
} // namespace ct

__constant__ ct::CTable c_tbl = ct::h_tbl;

// ======================= packed helpers ====================================
static __device__ __forceinline__ u64 pk(float x, float y) {
    u64 r; asm("mov.b64 %0,{%1,%2};" : "=l"(r) : "f"(x), "f"(y)); return r;
}
static __device__ __forceinline__ float2 upk(u64 v) {
    float2 f; asm("mov.b64 {%0,%1},%2;" : "=f"(f.x), "=f"(f.y) : "l"(v)); return f;
}
static __device__ __forceinline__ u64 fadd2(u64 a, u64 b) {
    u64 d; asm("add.rn.f32x2 %0,%1,%2;" : "=l"(d) : "l"(a), "l"(b)); return d;
}
static __device__ __forceinline__ u64 ffma2(u64 a, u64 b, u64 c) {
    u64 d; asm("fma.rn.f32x2 %0,%1,%2,%3;" : "=l"(d) : "l"(a), "l"(b), "l"(c)); return d;
}

// one gaussian, fused: acc += (aH*dth) * exp2(k*dth^2)
static __device__ __forceinline__ u64 gauss_acc(u64 acc, u64 thp, u64 nth0,
                                                u64 kkj, u64 aHj) {
    u64 r;
    asm("{\n\t"
        ".reg .b64 d,q,g;\n\t"
        ".reg .b32 al,ah;\n\t"
        "add.rn.f32x2 d,%1,%2;\n\t"        // dth = th - th0
        "mul.rn.f32x2 q,%3,d;\n\t"         // k*dth
        "mul.rn.f32x2 q,q,d;\n\t"          // arg = k*dth^2
        "mov.b64 {al,ah},q;\n\t"
        "ex2.approx.ftz.f32 al,al;\n\t"
        "ex2.approx.ftz.f32 ah,ah;\n\t"
        "mov.b64 g,{al,ah};\n\t"
        "mul.rn.f32x2 d,%4,d;\n\t"         // t = aH*dth
        "fma.rn.f32x2 %0,d,g,%5;\n\t"      // acc += t*e
        "}"
        : "=l"(r) : "l"(thp), "l"(nth0), "l"(kkj), "l"(aHj), "l"(acc));
    return r;
}

static __device__ __forceinline__ u64 forcing(int n, const u64* nth0,
                                              const u64* kk, const u64* aH) {
    float4 e = reinterpret_cast<const float4*>(c_tbl.v)[n];   // uniform LDC.128
    u64 thp = pk(e.x, e.y);
    u64 a0  = pk(e.z, e.w);
    u64 a1  = gauss_acc(0ull, thp, nth0[1], kk[1], aH[1]);
    a0 = gauss_acc(a0, thp, nth0[0], kk[0], aH[0]);
    a1 = gauss_acc(a1, thp, nth0[3], kk[3], aH[3]);
    a0 = gauss_acc(a0, thp, nth0[2], kk[2], aH[2]);
    a1 = gauss_acc(a1, thp, nth0[4], kk[4], aH[4]);
    return fadd2(a0, a1);
}

// ======================= main kernel =======================================
__global__ void __launch_bounds__(TPB, 8)
euler_kernel(const float* __restrict__ xin, const float* __restrict__ v0,
             float* __restrict__ out) {
    __shared__ float sparams[ROWSPB * 15];             // 7680 B
    __shared__ float schunk[CHUNK * CSTRIDE];          // 4224 B

    const int tid  = threadIdx.x;
    const int row0 = blockIdx.x * ROWSPB;

    // coalesced param staging: 128 rows x 15 floats = 480 float4
    {
        const float4* src = reinterpret_cast<const float4*>(xin + (size_t)row0 * 15);
        float4*       dst = reinterpret_cast<float4*>(sparams);
        #pragma unroll
        for (int k = 0; k < (ROWSPB * 15) / (4 * TPB); ++k)   // 7 full iters
            dst[tid + k * TPB] = src[tid + k * TPB];
        int rem = tid + ((ROWSPB * 15) / (4 * TPB)) * TPB;    // tail 32 float4
        if (rem < (ROWSPB * 15) / 4) dst[rem] = src[rem];
    }
    __syncthreads();

    const float H = 1.0f / 216.0f;
    u64 nth0[5], kk[5], aH[5];
    {
        const float* p0 = sparams + (2 * tid) * 15;
        const float* p1 = p0 + 15;
        #pragma unroll
        for (int j = 0; j < 5; ++j) {
            float a0 = p0[3 * j], b0 = p0[3 * j + 1], t0 = p0[3 * j + 2];
            float a1 = p1[3 * j], b1 = p1[3 * j + 1], t1 = p1[3 * j + 2];
            nth0[j] = pk(-t0, -t1);
            aH[j]   = pk(-H * a0, -H * a1);
            kk[j]   = pk(-1.4426950408889634f / (2.0f * b0 * b0),
                         -1.4426950408889634f / (2.0f * b1 * b1));
        }
    }
    const float omh = 1.0f - H;
    const u64 OMH2 = pk(omh, omh);

    u64 z0;
    {
        float2 vv = reinterpret_cast<const float2*>(v0)[(row0 >> 1) + tid];
        z0 = pk(vv.x, vv.y);
    }

    // ---- pass 1: min/max only --------------------------------------------
    float mn0 =  3.402823466e38f, mn1 =  3.402823466e38f;
    float mx0 = -3.402823466e38f, mx1 = -3.402823466e38f;
    {
        u64 z = z0;
        #pragma unroll 8
        for (int n = 0; n < NSTEPS; ++n) {
            u64 f = forcing(n, nth0, kk, aH);
            z = ffma2(z, OMH2, f);
            float2 zf = upk(z);
            mn0 = fminf(mn0, zf.x); mx0 = fmaxf(mx0, zf.x);
            mn1 = fminf(mn1, zf.y); mx1 = fmaxf(mx1, zf.y);
        }
    }
    u64 sc, bs;
    {
        float s0 = 0.042557f / (mx0 - mn0);
        float s1 = 0.042557f / (mx1 - mn1);
        sc = pk(s0, s1);
        bs = pk(fmaf(-mn0, s0, -0.01563f), fmaf(-mn1, s1, -0.01563f));
    }

    // ---- pass 2: bit-identical recompute + staged coalesced write --------
    {
        u64 z = z0;
        float* obase = out + (size_t)row0 * NSTEPS;
        for (int ch = 0; ch < NSTEPS / CHUNK; ++ch) {
            #pragma unroll
            for (int c = 0; c < CHUNK; ++c) {
                u64 f = forcing(ch * CHUNK + c, nth0, kk, aH);
                z = ffma2(z, OMH2, f);
                u64 o = ffma2(z, sc, bs);
                *reinterpret_cast<u64*>(&schunk[c * CSTRIDE + 2 * tid]) = o;
            }
            __syncthreads();
            #pragma unroll
            for (int k = 0; k < (ROWSPB * CHUNK) / TPB; ++k) {  // 16 iters
                int i = tid + k * TPB;
                int r = i >> 3;                 // local row 0..127
                int c = i & 7;                  // step-in-chunk
                obase[r * NSTEPS + ch * CHUNK + c] = schunk[c * CSTRIDE + r];
            }
            __syncthreads();
        }
    }
}

// ---------------------------------------------------------------------------
extern "C" void kernel_launch(void* const* d_in, const int* in_sizes, int n_in,
                              void* d_out, int out_size) {
    const float* x  = (const float*)d_in[0];   // (B, 15)
    const float* v0 = (const float*)d_in[1];   // (B,)
    float* out = (float*)d_out;                // (B, 216)

    int B = in_sizes[1];
    int nblocks = B / ROWSPB;                  // 131072 / 128 = 1024

    euler_kernel<<<nblocks, TPB>>>(x, v0, out);
}

// round 6
// speedup vs baseline: 2.8482x; 1.2325x over previous
#include <cuda_runtime.h>
#include <math.h>

// ---------------------------------------------------------------------------
// Euler_34093450396545, round 5.
// R4 post-mortem: MUFU-throughput-bound (10 ex2/step x 2 passes = 57us of 72us
// MUFU-busy at ~2.1GHz). Fix: SINGLE pass. Forcing (z-independent) is computed
// once, quantized to fp16 in smem (increment storage -> error random-walks on
// small values), min/max tracked on exact fp32 z in regs; epilogue re-scans
// z' = (1-H)z' + f_hat from smem and writes scaled output coalesced.
// Integration runs in a x1024-scaled domain so fp16 f_hat never goes subnormal
// (raw f ~ H*z0 ~ 2e-5 would be subnormal; scaled ~2e-2 is safely normal).
// 32-thread CTAs, 64 rows, 29.8KB smem -> 7 CTAs/SM. MUFU floor ~28.5us.
// ---------------------------------------------------------------------------

#define NSTEPS  216
#define TPB     32
#define ROWSPB  64           // 2 rows / thread, f32x2 packed
#define CHUNK   8
#define SSTRIDE 68           // staging pitch (= 4 mod 32 -> conflict-free transpose)

typedef unsigned long long u64;

// ======================= compile-time table ================================
namespace ct {
constexpr double PI = 3.14159265358979323846264338327950288;

constexpr double dsqrt(double x) {
    double y = x > 1.0 ? x : 1.0;
    for (int i = 0; i < 48; ++i) y = 0.5 * (y + x / y);
    return y;
}
constexpr double datan(double t) {
    double s = 1.0;
    for (int i = 0; i < 3; ++i) { t = t / (1.0 + dsqrt(1.0 + t * t)); s *= 2.0; }
    double t2 = t * t, r = 0.0;
    for (int k = 12; k >= 0; --k) r = 1.0 / (2.0 * k + 1.0) - t2 * r;
    return s * t * r;
}
constexpr double datan2(double y, double x) {
    if (x > 0.0) return datan(y / x);
    if (x < 0.0) return (y >= 0.0) ? datan(y / x) + PI : datan(y / x) - PI;
    return (y > 0.0) ? PI / 2 : -PI / 2;
}
constexpr double dsin(double x) {
    double x2 = x * x, term = x, sum = x;
    for (int k = 1; k <= 14; ++k) { term *= -x2 / ((2.0 * k) * (2.0 * k + 1.0)); sum += term; }
    return sum;
}
constexpr float f32(double x) { return (float)x; }

struct CTable { float v[NSTEPS][4]; };   // {th, th, 1024*H*z0, 1024*H*z0}

constexpr CTable make_table() {
    CTable T{};
    const float H     = f32(1.0 / 216.0);
    const float OMEGA = f32(2.0 * PI);
    const float PIH   = f32(0.5 * PI);
    float x = f32(-0.417750770388669);
    float y = f32(-0.9085616622823985);
    for (int n = 0; n < NSTEPS; ++n) {
        float th = f32(datan2((double)y, (double)x));
        float t   = f32((double)n / 216.0);
        float arg = f32((double)PIH * (double)t);
        float s   = f32(dsin((double)arg));
        float z0  = f32((double)f32(0.005) * (double)s);
        float hz  = f32((double)H * (double)z0);
        T.v[n][0] = th; T.v[n][1] = th;
        T.v[n][2] = hz * 1024.0f; T.v[n][3] = hz * 1024.0f;  // exact scaling
        float xx = f32((double)x * (double)x);
        float yy = f32((double)y * (double)y);
        float s2 = f32((double)xx + (double)yy);
        float r  = f32(dsqrt((double)s2));
        float al = f32(1.0 - (double)r);
        float ax = f32((double)al * (double)x);
        float oy = f32((double)OMEGA * (double)y);
        float fx = f32((double)ax - (double)oy);
        float ay = f32((double)al * (double)y);
        float ox = f32((double)OMEGA * (double)x);
        float fy = f32((double)ay + (double)ox);
        float hx = f32((double)H * (double)fx);
        float hy = f32((double)H * (double)fy);
        x = f32((double)x + (double)hx);
        y = f32((double)y + (double)hy);
    }
    return T;
}
constexpr CTable h_tbl = make_table();
} // namespace ct

__constant__ ct::CTable c_tbl = ct::h_tbl;

// ======================= packed helpers ====================================
static __device__ __forceinline__ u64 pk(float x, float y) {
    u64 r; asm("mov.b64 %0,{%1,%2};" : "=l"(r) : "f"(x), "f"(y)); return r;
}
static __device__ __forceinline__ float2 upk(u64 v) {
    float2 f; asm("mov.b64 {%0,%1},%2;" : "=f"(f.x), "=f"(f.y) : "l"(v)); return f;
}
static __device__ __forceinline__ u64 fadd2(u64 a, u64 b) {
    u64 d; asm("add.rn.f32x2 %0,%1,%2;" : "=l"(d) : "l"(a), "l"(b)); return d;
}
static __device__ __forceinline__ u64 ffma2(u64 a, u64 b, u64 c) {
    u64 d; asm("fma.rn.f32x2 %0,%1,%2,%3;" : "=l"(d) : "l"(a), "l"(b), "l"(c)); return d;
}
// {f32,f32} -> f16x2 (lo = first arg)
static __device__ __forceinline__ unsigned int f32x2_to_h2(u64 v) {
    unsigned int h;
    asm("{.reg .b32 lo,hi;\n\t"
        "mov.b64 {lo,hi},%1;\n\t"
        "cvt.rn.f16x2.f32 %0,hi,lo;}\n\t" : "=r"(h) : "l"(v));
    return h;
}
// f16x2 -> packed f32x2
static __device__ __forceinline__ u64 h2_to_f32x2(unsigned int h) {
    u64 v;
    asm("{.reg .b16 l,h;\n\t"
        ".reg .b32 lo,hi;\n\t"
        "mov.b32 {l,h},%1;\n\t"
        "cvt.f32.f16 lo,l;\n\t"
        "cvt.f32.f16 hi,h;\n\t"
        "mov.b64 %0,{lo,hi};}\n\t" : "=l"(v) : "r"(h));
    return v;
}

// one gaussian, fused: acc += (aH*dth) * exp2(k*dth^2)
static __device__ __forceinline__ u64 gauss_acc(u64 acc, u64 thp, u64 nth0,
                                                u64 kkj, u64 aHj) {
    u64 r;
    asm("{\n\t"
        ".reg .b64 d,q,g;\n\t"
        ".reg .b32 al,ah;\n\t"
        "add.rn.f32x2 d,%1,%2;\n\t"        // dth = th - th0
        "mul.rn.f32x2 q,%3,d;\n\t"         // k*dth
        "mul.rn.f32x2 q,q,d;\n\t"          // arg = k*dth^2
        "mov.b64 {al,ah},q;\n\t"
        "ex2.approx.ftz.f32 al,al;\n\t"
        "ex2.approx.ftz.f32 ah,ah;\n\t"
        "mov.b64 g,{al,ah};\n\t"
        "mul.rn.f32x2 d,%4,d;\n\t"         // t = aH*dth
        "fma.rn.f32x2 %0,d,g,%5;\n\t"      // acc += t*e
        "}"
        : "=l"(r) : "l"(thp), "l"(nth0), "l"(kkj), "l"(aHj), "l"(acc));
    return r;
}

// scaled forcing for step n: 1024*(H*z0_n - H*sum(gauss))  [aH pre-scaled]
static __device__ __forceinline__ u64 forcing(int n, const u64* nth0,
                                              const u64* kk, const u64* aH) {
    float4 e = reinterpret_cast<const float4*>(c_tbl.v)[n];   // uniform LDC.128
    u64 thp = pk(e.x, e.y);
    u64 a0  = pk(e.z, e.w);
    u64 a1  = gauss_acc(0ull, thp, nth0[1], kk[1], aH[1]);
    a0 = gauss_acc(a0, thp, nth0[0], kk[0], aH[0]);
    a1 = gauss_acc(a1, thp, nth0[3], kk[3], aH[3]);
    a0 = gauss_acc(a0, thp, nth0[2], kk[2], aH[2]);
    a1 = gauss_acc(a1, thp, nth0[4], kk[4], aH[4]);
    return fadd2(a0, a1);
}

// ======================= main kernel =======================================
__global__ void __launch_bounds__(TPB)
euler_kernel(const float* __restrict__ xin, const float* __restrict__ v0,
             float* __restrict__ out) {
    __shared__ unsigned int sF[NSTEPS * TPB];       // 27648 B: f16x2 forcings
    __shared__ float sStage[CHUNK * SSTRIDE];       //  2176 B: output staging

    const int tid  = threadIdx.x;
    const int row0 = blockIdx.x * ROWSPB;

    // coalesced param staging via sF region (64 rows x 15 f32 = 240 float4)
    {
        const float4* src = reinterpret_cast<const float4*>(xin + (size_t)row0 * 15);
        float4*       dst = reinterpret_cast<float4*>(sF);
        #pragma unroll
        for (int k = 0; k < 7; ++k) dst[tid + k * TPB] = src[tid + k * TPB];
        if (tid + 7 * TPB < 240) dst[tid + 7 * TPB] = src[tid + 7 * TPB];
    }
    __syncwarp();

    const float HS = 1024.0f / 216.0f;              // 1024*H (exact x1024)
    u64 nth0[5], kk[5], aH[5];
    {
        const float* p0 = reinterpret_cast<const float*>(sF) + (2 * tid) * 15;
        const float* p1 = p0 + 15;
        #pragma unroll
        for (int j = 0; j < 5; ++j) {
            float a0 = p0[3 * j], b0 = p0[3 * j + 1], t0 = p0[3 * j + 2];
            float a1 = p1[3 * j], b1 = p1[3 * j + 1], t1 = p1[3 * j + 2];
            nth0[j] = pk(-t0, -t1);
            aH[j]   = pk(-HS * a0, -HS * a1);
            kk[j]   = pk(-1.4426950408889634f / (2.0f * b0 * b0),
                         -1.4426950408889634f / (2.0f * b1 * b1));
        }
    }
    const float omh = 1.0f - 1.0f / 216.0f;
    const u64 OMH2 = pk(omh, omh);

    u64 Z0;   // z scaled by 1024
    {
        float2 vv = reinterpret_cast<const float2*>(v0)[(row0 >> 1) + tid];
        Z0 = pk(vv.x * 1024.0f, vv.y * 1024.0f);
    }
    __syncwarp();   // params consumed; sF free for f16 forcings

    // ---- single pass: exact z for min/max, fp16 forcing stored -----------
    float mn0 =  3.402823466e38f, mn1 =  3.402823466e38f;
    float mx0 = -3.402823466e38f, mx1 = -3.402823466e38f;
    {
        u64 Z = Z0;
        #pragma unroll 8
        for (int n = 0; n < NSTEPS; ++n) {
            u64 f = forcing(n, nth0, kk, aH);
            sF[n * TPB + tid] = f32x2_to_h2(f);
            Z = ffma2(Z, OMH2, f);
            float2 zf = upk(Z);
            mn0 = fminf(mn0, zf.x); mx0 = fmaxf(mx0, zf.x);
            mn1 = fminf(mn1, zf.y); mx1 = fmaxf(mx1, zf.y);
        }
    }
    u64 sc, bs;
    {
        float s0 = 0.042557f / (mx0 - mn0);
        float s1 = 0.042557f / (mx1 - mn1);
        sc = pk(s0, s1);
        bs = pk(fmaf(-mn0, s0, -0.01563f), fmaf(-mn1, s1, -0.01563f));
    }

    // ---- epilogue: re-scan quantized forcing, scale, coalesced write -----
    {
        u64 Z = Z0;
        float* obase = out + (size_t)row0 * NSTEPS;
        for (int ch = 0; ch < NSTEPS / CHUNK; ++ch) {
            #pragma unroll
            for (int c = 0; c < CHUNK; ++c) {
                int n = ch * CHUNK + c;
                u64 f = h2_to_f32x2(sF[n * TPB + tid]);   // own thread's data
                Z = ffma2(Z, OMH2, f);
                u64 o = ffma2(Z, sc, bs);
                *reinterpret_cast<u64*>(&sStage[c * SSTRIDE + 2 * tid]) = o;
            }
            __syncwarp();
            #pragma unroll
            for (int k = 0; k < (ROWSPB * CHUNK) / TPB; ++k) {  // 16 iters
                int i = tid + k * TPB;
                int r = i >> 3;                 // local row 0..63
                int c = i & 7;                  // step-in-chunk
                obase[r * NSTEPS + ch * CHUNK + c] = sStage[c * SSTRIDE + r];
            }
            __syncwarp();
        }
    }
}

// ---------------------------------------------------------------------------
extern "C" void kernel_launch(void* const* d_in, const int* in_sizes, int n_in,
                              void* d_out, int out_size) {
    const float* x  = (const float*)d_in[0];   // (B, 15)
    const float* v0 = (const float*)d_in[1];   // (B,)
    float* out = (float*)d_out;                // (B, 216)

    int B = in_sizes[1];
    int nblocks = B / ROWSPB;                  // 131072 / 64 = 2048

    cudaFuncSetAttribute(euler_kernel,
                         cudaFuncAttributePreferredSharedMemoryCarveout,
                         cudaSharedmemCarveoutMaxShared);
    euler_kernel<<<nblocks, TPB>>>(x, v0, out);
}

// round 9
// speedup vs baseline: 3.2102x; 1.1271x over previous
#include <cuda_runtime.h>
#include <math.h>

// ---------------------------------------------------------------------------
// Euler_34093450396545, round 7 (R6 resubmit; compile fix only).
// R6 failed to build: device call to host constexpr function ct::c54().
// Fix: evaluate it into file-scope constexpr floats (value-used -> legal in
// device code, becomes an immediate). Design unchanged:
// parallel-in-time over 4 warps x 54-step segments of the same 64 rows,
// fp16-quantized forcing in smem, boundary combine, cheap replays.
// ---------------------------------------------------------------------------

#define NSTEPS  216
#define TPB     128          // 4 warps
#define NSEG    4
#define SEGLEN  54
#define ROWSPB  64           // 2 rows / thread-lane, f32x2 packed
#define SSTRIDE 68           // staging pitch: =4 mod 32 -> conflict-free

typedef unsigned long long u64;
typedef unsigned int u32;

// ======================= compile-time table ================================
namespace ct {
constexpr double PI = 3.14159265358979323846264338327950288;

constexpr double dsqrt(double x) {
    double y = x > 1.0 ? x : 1.0;
    for (int i = 0; i < 48; ++i) y = 0.5 * (y + x / y);
    return y;
}
constexpr double datan(double t) {
    double s = 1.0;
    for (int i = 0; i < 3; ++i) { t = t / (1.0 + dsqrt(1.0 + t * t)); s *= 2.0; }
    double t2 = t * t, r = 0.0;
    for (int k = 12; k >= 0; --k) r = 1.0 / (2.0 * k + 1.0) - t2 * r;
    return s * t * r;
}
constexpr double datan2(double y, double x) {
    if (x > 0.0) return datan(y / x);
    if (x < 0.0) return (y >= 0.0) ? datan(y / x) + PI : datan(y / x) - PI;
    return (y > 0.0) ? PI / 2 : -PI / 2;
}
constexpr double dsin(double x) {
    double x2 = x * x, term = x, sum = x;
    for (int k = 1; k <= 14; ++k) { term *= -x2 / ((2.0 * k) * (2.0 * k + 1.0)); sum += term; }
    return sum;
}
constexpr float f32(double x) { return (float)x; }

struct CTable { float v[NSTEPS][4]; };   // {th, th, 1024*H*z0, 1024*H*z0}

constexpr CTable make_table() {
    CTable T{};
    const float H     = f32(1.0 / 216.0);
    const float OMEGA = f32(2.0 * PI);
    const float PIH   = f32(0.5 * PI);
    float x = f32(-0.417750770388669);
    float y = f32(-0.9085616622823985);
    for (int n = 0; n < NSTEPS; ++n) {
        float th = f32(datan2((double)y, (double)x));
        float t   = f32((double)n / 216.0);
        float arg = f32((double)PIH * (double)t);
        float s   = f32(dsin((double)arg));
        float z0  = f32((double)f32(0.005) * (double)s);
        float hz  = f32((double)H * (double)z0);
        T.v[n][0] = th; T.v[n][1] = th;
        T.v[n][2] = hz * 1024.0f; T.v[n][3] = hz * 1024.0f;
        float xx = f32((double)x * (double)x);
        float yy = f32((double)y * (double)y);
        float s2 = f32((double)xx + (double)yy);
        float r  = f32(dsqrt((double)s2));
        float al = f32(1.0 - (double)r);
        float ax = f32((double)al * (double)x);
        float oy = f32((double)OMEGA * (double)y);
        float fx = f32((double)ax - (double)oy);
        float ay = f32((double)al * (double)y);
        float ox = f32((double)OMEGA * (double)x);
        float fy = f32((double)ay + (double)ox);
        float hx = f32((double)H * (double)fx);
        float hy = f32((double)H * (double)fy);
        x = f32((double)x + (double)hx);
        y = f32((double)y + (double)hy);
    }
    return T;
}
constexpr CTable h_tbl = make_table();

constexpr float c54() {
    float omh = f32(1.0 - (double)f32(1.0 / 216.0));  // 1 - H in fp32
    double p = 1.0;
    for (int i = 0; i < SEGLEN; ++i) p *= (double)omh;
    return (float)p;
}
} // namespace ct

// file-scope constexpr VALUES (legal to value-use in device code)
constexpr float C54_F = ct::c54();
constexpr float OMH_F = 1.0f - 1.0f / 216.0f;
constexpr float HS_F  = 1024.0f / 216.0f;          // 1024*H

__constant__ ct::CTable c_tbl = ct::h_tbl;

// ======================= packed helpers ====================================
static __device__ __forceinline__ u64 pk(float x, float y) {
    u64 r; asm("mov.b64 %0,{%1,%2};" : "=l"(r) : "f"(x), "f"(y)); return r;
}
static __device__ __forceinline__ float2 upk(u64 v) {
    float2 f; asm("mov.b64 {%0,%1},%2;" : "=f"(f.x), "=f"(f.y) : "l"(v)); return f;
}
static __device__ __forceinline__ u64 fadd2(u64 a, u64 b) {
    u64 d; asm("add.rn.f32x2 %0,%1,%2;" : "=l"(d) : "l"(a), "l"(b)); return d;
}
static __device__ __forceinline__ u64 ffma2(u64 a, u64 b, u64 c) {
    u64 d; asm("fma.rn.f32x2 %0,%1,%2,%3;" : "=l"(d) : "l"(a), "l"(b), "l"(c)); return d;
}
static __device__ __forceinline__ u32 f32x2_to_h2(u64 v) {
    u32 h;
    asm("{.reg .b32 lo,hi;\n\t"
        "mov.b64 {lo,hi},%1;\n\t"
        "cvt.rn.f16x2.f32 %0,hi,lo;}\n\t" : "=r"(h) : "l"(v));
    return h;
}
static __device__ __forceinline__ u64 h2_to_f32x2(u32 h) {
    u64 v;
    asm("{.reg .b16 l,h;\n\t"
        ".reg .b32 lo,hi;\n\t"
        "mov.b32 {l,h},%1;\n\t"
        "cvt.f32.f16 lo,l;\n\t"
        "cvt.f32.f16 hi,h;\n\t"
        "mov.b64 %0,{lo,hi};}\n\t" : "=l"(v) : "r"(h));
    return v;
}

static __device__ __forceinline__ u64 gauss_acc(u64 acc, u64 thp, u64 nth0,
                                                u64 kkj, u64 aHj) {
    u64 r;
    asm("{\n\t"
        ".reg .b64 d,q,g;\n\t"
        ".reg .b32 al,ah;\n\t"
        "add.rn.f32x2 d,%1,%2;\n\t"
        "mul.rn.f32x2 q,%3,d;\n\t"
        "mul.rn.f32x2 q,q,d;\n\t"
        "mov.b64 {al,ah},q;\n\t"
        "ex2.approx.ftz.f32 al,al;\n\t"
        "ex2.approx.ftz.f32 ah,ah;\n\t"
        "mov.b64 g,{al,ah};\n\t"
        "mul.rn.f32x2 d,%4,d;\n\t"
        "fma.rn.f32x2 %0,d,g,%5;\n\t"
        "}"
        : "=l"(r) : "l"(thp), "l"(nth0), "l"(kkj), "l"(aHj), "l"(acc));
    return r;
}

static __device__ __forceinline__ u64 forcing(int n, const u64* nth0,
                                              const u64* kk, const u64* aH) {
    float4 e = reinterpret_cast<const float4*>(c_tbl.v)[n];
    u64 thp = pk(e.x, e.y);
    u64 a0  = pk(e.z, e.w);
    u64 a1  = gauss_acc(0ull, thp, nth0[1], kk[1], aH[1]);
    a0 = gauss_acc(a0, thp, nth0[0], kk[0], aH[0]);
    a1 = gauss_acc(a1, thp, nth0[3], kk[3], aH[3]);
    a0 = gauss_acc(a0, thp, nth0[2], kk[2], aH[2]);
    a1 = gauss_acc(a1, thp, nth0[4], kk[4], aH[4]);
    return fadd2(a0, a1);
}

// ======================= main kernel =======================================
// smem map (bytes):
//   [0, 27648)      sF: f16x2 forcing, sF[n*32 + lane]   (also param stage)
//   [27648, 36352)  staging (4 warps x 2176B) aliased with exchange:
//       xFseg[4][32] u64 | xmn[4][32] u64 | xmx[4][32] u64
__global__ void __launch_bounds__(TPB, 5)
euler_kernel(const float* __restrict__ xin, const float* __restrict__ v0,
             float* __restrict__ out) {
    __shared__ __align__(16) unsigned char smem_raw[36352];
    u32*   sF     = reinterpret_cast<u32*>(smem_raw);
    float* sStage = reinterpret_cast<float*>(smem_raw + 27648);
    u64*   xFseg  = reinterpret_cast<u64*>(smem_raw + 27648);
    u64*   xmn    = xFseg + NSEG * 32;
    u64*   xmx    = xmn  + NSEG * 32;

    const int tid  = threadIdx.x;
    const int lane = tid & 31;
    const int wid  = tid >> 5;
    const int row0 = blockIdx.x * ROWSPB;

    // coalesced param staging into sF region: 64 rows x 15 f32 = 240 float4
    {
        const float4* src = reinterpret_cast<const float4*>(xin + (size_t)row0 * 15);
        float4*       dst = reinterpret_cast<float4*>(sF);
        dst[tid] = src[tid];                       // 0..127
        if (tid + TPB < 240) dst[tid + TPB] = src[tid + TPB];
    }
    __syncthreads();

    u64 nth0[5], kk[5], aH[5];
    {
        const float* p0 = reinterpret_cast<const float*>(sF) + (2 * lane) * 15;
        const float* p1 = p0 + 15;
        #pragma unroll
        for (int j = 0; j < 5; ++j) {
            float a0 = p0[3 * j], b0 = p0[3 * j + 1], t0 = p0[3 * j + 2];
            float a1 = p1[3 * j], b1 = p1[3 * j + 1], t1 = p1[3 * j + 2];
            nth0[j] = pk(-t0, -t1);
            aH[j]   = pk(-HS_F * a0, -HS_F * a1);
            kk[j]   = pk(-1.4426950408889634f / (2.0f * b0 * b0),
                         -1.4426950408889634f / (2.0f * b1 * b1));
        }
    }
    const u64 OMH2 = pk(OMH_F, OMH_F);
    const u64 C54  = pk(C54_F, C54_F);

    u64 Z0;   // z scaled by 1024
    {
        float2 vv = reinterpret_cast<const float2*>(v0)[(row0 >> 1) + lane];
        Z0 = pk(vv.x * 1024.0f, vv.y * 1024.0f);
    }
    __syncthreads();    // everyone done reading params; sF free

    const int n0 = wid * SEGLEN;

    // ---- Phase A: forcings for my 54-step segment + segment sum ----------
    u64 Fseg = 0ull;
    #pragma unroll 3
    for (int i = 0; i < SEGLEN; ++i) {
        int n = n0 + i;
        u64 f = forcing(n, nth0, kk, aH);
        sF[n * 32 + lane] = f32x2_to_h2(f);
        Fseg = ffma2(Fseg, OMH2, f);       // = sum c^{53-i} f_i
    }
    __syncthreads();

    // ---- boundary combine: z at my segment start -------------------------
    xFseg[wid * 32 + lane] = Fseg;
    __syncthreads();
    u64 Zs = Z0;
    #pragma unroll
    for (int u = 0; u < NSEG - 1; ++u)
        if (u < wid) Zs = ffma2(Zs, C54, xFseg[u * 32 + lane]);

    // ---- C1: replay quantized forcings for min/max -----------------------
    float mn0 =  3.402823466e38f, mn1 =  3.402823466e38f;
    float mx0 = -3.402823466e38f, mx1 = -3.402823466e38f;
    {
        u64 Z = Zs;
        #pragma unroll 6
        for (int i = 0; i < SEGLEN; ++i) {
            u64 f = h2_to_f32x2(sF[(n0 + i) * 32 + lane]);
            Z = ffma2(Z, OMH2, f);
            float2 zf = upk(Z);
            mn0 = fminf(mn0, zf.x); mx0 = fmaxf(mx0, zf.x);
            mn1 = fminf(mn1, zf.y); mx1 = fmaxf(mx1, zf.y);
        }
    }
    xmn[wid * 32 + lane] = pk(mn0, mn1);
    xmx[wid * 32 + lane] = pk(mx0, mx1);
    __syncthreads();
    u64 sc, bs;
    {
        #pragma unroll
        for (int u = 0; u < NSEG; ++u) {
            float2 a = upk(xmn[u * 32 + lane]);
            float2 b = upk(xmx[u * 32 + lane]);
            mn0 = fminf(mn0, a.x); mn1 = fminf(mn1, a.y);
            mx0 = fmaxf(mx0, b.x); mx1 = fmaxf(mx1, b.y);
        }
        float s0 = 0.042557f / (mx0 - mn0);
        float s1 = 0.042557f / (mx1 - mn1);
        sc = pk(s0, s1);
        bs = pk(fmaf(-mn0, s0, -0.01563f), fmaf(-mn1, s1, -0.01563f));
    }
    __syncthreads();    // exchange region done; staging may now overwrite it

    // ---- C2: replay + scale + per-warp staged coalesced write ------------
    {
        u64 Z = Zs;
        float* obase  = out + (size_t)row0 * NSTEPS;
        float* stageW = sStage + wid * (8 * SSTRIDE);
        #pragma unroll
        for (int ch = 0; ch < 7; ++ch) {                 // 6x8 + 1x6 = 54
            const int cl = (ch < 6) ? 8 : 6;
            #pragma unroll
            for (int c = 0; c < 8; ++c) {
                if (c < cl) {
                    int n = n0 + ch * 8 + c;
                    u64 f = h2_to_f32x2(sF[n * 32 + lane]);
                    Z = ffma2(Z, OMH2, f);
                    u64 o = ffma2(Z, sc, bs);
                    *reinterpret_cast<u64*>(&stageW[c * SSTRIDE + 2 * lane]) = o;
                }
            }
            __syncwarp();
            #pragma unroll
            for (int k = 0; k < 16; ++k) {
                int i = lane + 32 * k;
                int r = i >> 3;                          // local row 0..63
                int c = i & 7;
                if (c < cl)
                    obase[r * NSTEPS + n0 + ch * 8 + c] = stageW[c * SSTRIDE + r];
            }
            __syncwarp();
        }
    }
}

// ---------------------------------------------------------------------------
extern "C" void kernel_launch(void* const* d_in, const int* in_sizes, int n_in,
                              void* d_out, int out_size) {
    const float* x  = (const float*)d_in[0];   // (B, 15)
    const float* v0 = (const float*)d_in[1];   // (B,)
    float* out = (float*)d_out;                // (B, 216)

    int B = in_sizes[1];
    int nblocks = B / ROWSPB;                  // 131072 / 64 = 2048

    cudaFuncSetAttribute(euler_kernel,
                         cudaFuncAttributePreferredSharedMemoryCarveout,
                         cudaSharedmemCarveoutMaxShared);
    euler_kernel<<<nblocks, TPB>>>(x, v0, out);
}